// round 1
// baseline (speedup 1.0000x reference)
#include <cuda_runtime.h>
#include <cstdint>

// Problem constants (fixed shapes from reference setup_inputs)
#define BS   32
#define C    256
#define HW   4096          // 64*64
#define HID  32            // C / R
#define KK   2
#define NPLANES (BS * C)   // 8192

// Scratch in device globals (no allocations allowed)
__device__ float g_pooled[NPLANES];                 // [BS, C]
__device__ float g_coefA[BS * KK * C];              // scale a[b,k,c]
__device__ float g_coefB[BS * KK * C];              // bias  b[b,k,c]

// ---------------------------------------------------------------------------
// Kernel 1: mean pool over H*W. One CTA per (b,c) plane. 256 threads,
// each reads 4x float4 = 16 floats. Warp-shuffle + smem reduce.
// ---------------------------------------------------------------------------
__global__ __launch_bounds__(256) void pool_kernel(const float* __restrict__ x) {
    const int p = blockIdx.x;                  // plane index = b*C + c
    const int t = threadIdx.x;
    const float4* __restrict__ x4 = reinterpret_cast<const float4*>(x) + (size_t)p * (HW / 4);

    float s = 0.f;
#pragma unroll
    for (int it = 0; it < 4; ++it) {
        float4 v = x4[t + it * 256];
        s += (v.x + v.y) + (v.z + v.w);
    }
    // warp reduce
#pragma unroll
    for (int o = 16; o > 0; o >>= 1) s += __shfl_down_sync(0xffffffffu, s, o);

    __shared__ float ws[8];
    if ((t & 31) == 0) ws[t >> 5] = s;
    __syncthreads();
    if (t < 8) {
        float v = ws[t];
#pragma unroll
        for (int o = 4; o > 0; o >>= 1) v += __shfl_down_sync(0xffu, v, o);
        if (t == 0) g_pooled[p] = v * (1.0f / (float)HW);
    }
}

// ---------------------------------------------------------------------------
// Kernel 2: coefficients. One CTA per batch element (32 CTAs, 256 threads).
//   h = relu(pooled @ w1^T + b1)                       [HID]
//   z[k,o] = sum_h w2[k,o,h]*h[h] + b2[k,o]            o in [0, 2C)
//   delta  = 2*sigmoid(z) - 1 = tanh(z/2)
//   a[b,k,c] = (k==0) + 1.0 * delta[k, 2c]
//   b[b,k,c] = (k==0) + 0.5 * delta[k, 2c+1]
// ---------------------------------------------------------------------------
__global__ __launch_bounds__(256) void coef_kernel(const float* __restrict__ w1,
                                                   const float* __restrict__ b1,
                                                   const float* __restrict__ w2,
                                                   const float* __restrict__ b2) {
    const int b = blockIdx.x;
    const int t = threadIdx.x;

    __shared__ float sp[C];    // pooled row
    __shared__ float sh[HID];  // hidden

    sp[t] = g_pooled[b * C + t];
    __syncthreads();

    if (t < HID) {
        float acc = b1[t];
        const float* __restrict__ w1r = w1 + t * C;
#pragma unroll 8
        for (int c = 0; c < C; ++c) acc = fmaf(sp[c], w1r[c], acc);
        sh[t] = fmaxf(acc, 0.f);
    }
    __syncthreads();

    // 1024 total outputs (K*2C), 4 per thread
#pragma unroll
    for (int rep = 0; rep < 4; ++rep) {
        const int o = t + rep * 256;       // flat over [K, 2C]
        const int k  = o >> 9;             // o / 512
        const int oo = o & 511;            // o % 512
        float acc = b2[o];
        const float* __restrict__ w2r = w2 + o * HID;
#pragma unroll
        for (int h = 0; h < HID; ++h) acc = fmaf(sh[h], w2r[h], acc);
        const float delta = tanhf(0.5f * acc);   // == 2*sigmoid(acc) - 1
        const float init = (k == 0) ? 1.0f : 0.0f;
        const int c = oo >> 1;
        const int idx = (b * KK + k) * C + c;
        if ((oo & 1) == 0) g_coefA[idx] = init + delta;          // LAMBDA_ALPHA = 1.0
        else               g_coefB[idx] = init + 0.5f * delta;   // LAMBDA_BETA  = 0.5
    }
}

// ---------------------------------------------------------------------------
// Kernel 3: out[b,c,:,:] = max(x*a0 + b0, x*a1 + b1). One CTA per plane.
// 256 threads x 4 float4 each.
// ---------------------------------------------------------------------------
__global__ __launch_bounds__(256) void apply_kernel(const float* __restrict__ x,
                                                    float* __restrict__ out) {
    const int p = blockIdx.x;        // b*C + c
    const int t = threadIdx.x;
    const int b = p >> 8;
    const int c = p & 255;

    const float a0 = g_coefA[(b * KK + 0) * C + c];
    const float a1 = g_coefA[(b * KK + 1) * C + c];
    const float q0 = g_coefB[(b * KK + 0) * C + c];
    const float q1 = g_coefB[(b * KK + 1) * C + c];

    const float4* __restrict__ x4 = reinterpret_cast<const float4*>(x) + (size_t)p * (HW / 4);
    float4* __restrict__ o4       = reinterpret_cast<float4*>(out)     + (size_t)p * (HW / 4);

#pragma unroll
    for (int it = 0; it < 4; ++it) {
        const int i = t + it * 256;
        float4 v = x4[i];
        float4 r;
        r.x = fmaxf(fmaf(v.x, a0, q0), fmaf(v.x, a1, q1));
        r.y = fmaxf(fmaf(v.y, a0, q0), fmaf(v.y, a1, q1));
        r.z = fmaxf(fmaf(v.z, a0, q0), fmaf(v.z, a1, q1));
        r.w = fmaxf(fmaf(v.w, a0, q0), fmaf(v.w, a1, q1));
        o4[i] = r;
    }
}

extern "C" void kernel_launch(void* const* d_in, const int* in_sizes, int n_in,
                              void* d_out, int out_size) {
    const float* x  = (const float*)d_in[0];
    const float* w1 = (const float*)d_in[1];
    const float* b1 = (const float*)d_in[2];
    const float* w2 = (const float*)d_in[3];
    const float* b2 = (const float*)d_in[4];
    float* out = (float*)d_out;

    pool_kernel<<<NPLANES, 256>>>(x);
    coef_kernel<<<BS, 256>>>(w1, b1, w2, b2);
    apply_kernel<<<NPLANES, 256>>>(x, out);
}

// round 2
// speedup vs baseline: 1.0934x; 1.0934x over previous
#include <cuda_runtime.h>
#include <cstdint>

// Problem constants (fixed shapes from reference setup_inputs)
#define BS   32
#define C    256
#define HW   4096          // 64*64
#define HID  32            // C / R
#define KK   2
#define NPLANES (BS * C)   // 8192

// Scratch in device globals (no allocations allowed)
__device__ float g_pooled[NPLANES];                 // [BS, C]
__device__ float g_coefA[BS * KK * C];              // scale a[b,k,c]
__device__ float g_coefB[BS * KK * C];              // bias  b[b,k,c]

// ---------------------------------------------------------------------------
// Kernel 1: mean pool over H*W. One CTA per (b,c) plane. 256 threads,
// each reads 4x float4 = 16 floats. Warp-shuffle + smem reduce.
// Reads use default .ca policy so x lands in L2 for the apply pass.
// ---------------------------------------------------------------------------
__global__ __launch_bounds__(256) void pool_kernel(const float* __restrict__ x) {
    const int p = blockIdx.x;                  // plane index = b*C + c
    const int t = threadIdx.x;
    const float4* __restrict__ x4 = reinterpret_cast<const float4*>(x) + (size_t)p * (HW / 4);

    // Front-batch all 4 loads (MLP=4)
    float4 v0 = x4[t];
    float4 v1 = x4[t + 256];
    float4 v2 = x4[t + 512];
    float4 v3 = x4[t + 768];

    float s = ((v0.x + v0.y) + (v0.z + v0.w))
            + ((v1.x + v1.y) + (v1.z + v1.w))
            + ((v2.x + v2.y) + (v2.z + v2.w))
            + ((v3.x + v3.y) + (v3.z + v3.w));

    // warp reduce
#pragma unroll
    for (int o = 16; o > 0; o >>= 1) s += __shfl_down_sync(0xffffffffu, s, o);

    __shared__ float ws[8];
    if ((t & 31) == 0) ws[t >> 5] = s;
    __syncthreads();
    if (t < 8) {
        float v = ws[t];
#pragma unroll
        for (int o = 4; o > 0; o >>= 1) v += __shfl_down_sync(0xffu, v, o);
        if (t == 0) g_pooled[p] = v * (1.0f / (float)HW);
    }
}

// ---------------------------------------------------------------------------
// Kernel 2: coefficients. One CTA per batch element (32 CTAs, 256 threads).
//   h = relu(pooled @ w1^T + b1)                       [HID]
//   z[k,o] = sum_h w2[k,o,h]*h[h] + b2[k,o]            o in [0, 2C)
//   delta  = 2*sigmoid(z) - 1 = tanh(z/2)
//   a[b,k,c] = (k==0) + 1.0 * delta[k, 2c]
//   b[b,k,c] = (k==0) + 0.5 * delta[k, 2c+1]
// ---------------------------------------------------------------------------
__global__ __launch_bounds__(256) void coef_kernel(const float* __restrict__ w1,
                                                   const float* __restrict__ b1,
                                                   const float* __restrict__ w2,
                                                   const float* __restrict__ b2) {
    const int b = blockIdx.x;
    const int t = threadIdx.x;

    __shared__ float sp[C];    // pooled row
    __shared__ float sh[HID];  // hidden

    sp[t] = g_pooled[b * C + t];
    __syncthreads();

    if (t < HID) {
        float acc = b1[t];
        const float* __restrict__ w1r = w1 + t * C;
#pragma unroll 8
        for (int c = 0; c < C; ++c) acc = fmaf(sp[c], w1r[c], acc);
        sh[t] = fmaxf(acc, 0.f);
    }
    __syncthreads();

    // 1024 total outputs (K*2C), 4 per thread
#pragma unroll
    for (int rep = 0; rep < 4; ++rep) {
        const int o = t + rep * 256;       // flat over [K, 2C]
        const int k  = o >> 9;             // o / 512
        const int oo = o & 511;            // o % 512
        float acc = b2[o];
        const float* __restrict__ w2r = w2 + o * HID;
#pragma unroll
        for (int h = 0; h < HID; ++h) acc = fmaf(sh[h], w2r[h], acc);
        const float delta = tanhf(0.5f * acc);   // == 2*sigmoid(acc) - 1
        const float init = (k == 0) ? 1.0f : 0.0f;
        const int c = oo >> 1;
        const int idx = (b * KK + k) * C + c;
        if ((oo & 1) == 0) g_coefA[idx] = init + delta;          // LAMBDA_ALPHA = 1.0
        else               g_coefB[idx] = init + 0.5f * delta;   // LAMBDA_BETA  = 0.5
    }
}

// ---------------------------------------------------------------------------
// Kernel 3: out[b,c,:,:] = max(x*a0 + b0, x*a1 + b1).
// One CTA per plane, processed in REVERSE plane order so the most recently
// cached tail of x (left in L2 by pool_kernel) is consumed first.
// Output written with __stcs (evict-first) so out never evicts x from L2.
// All 4 float4 loads are front-batched for MLP=4.
// ---------------------------------------------------------------------------
__global__ __launch_bounds__(256) void apply_kernel(const float* __restrict__ x,
                                                    float* __restrict__ out) {
    const int p = (NPLANES - 1) - blockIdx.x;   // reverse traversal
    const int t = threadIdx.x;
    const int b = p >> 8;
    const int c = p & 255;

    const float a0 = g_coefA[(b * KK + 0) * C + c];
    const float a1 = g_coefA[(b * KK + 1) * C + c];
    const float q0 = g_coefB[(b * KK + 0) * C + c];
    const float q1 = g_coefB[(b * KK + 1) * C + c];

    const float4* __restrict__ x4 = reinterpret_cast<const float4*>(x) + (size_t)p * (HW / 4);
    float4* __restrict__ o4       = reinterpret_cast<float4*>(out)     + (size_t)p * (HW / 4);

    // Front-batch loads
    float4 v0 = x4[t];
    float4 v1 = x4[t + 256];
    float4 v2 = x4[t + 512];
    float4 v3 = x4[t + 768];

    float4 r0, r1, r2, r3;
    r0.x = fmaxf(fmaf(v0.x, a0, q0), fmaf(v0.x, a1, q1));
    r0.y = fmaxf(fmaf(v0.y, a0, q0), fmaf(v0.y, a1, q1));
    r0.z = fmaxf(fmaf(v0.z, a0, q0), fmaf(v0.z, a1, q1));
    r0.w = fmaxf(fmaf(v0.w, a0, q0), fmaf(v0.w, a1, q1));
    r1.x = fmaxf(fmaf(v1.x, a0, q0), fmaf(v1.x, a1, q1));
    r1.y = fmaxf(fmaf(v1.y, a0, q0), fmaf(v1.y, a1, q1));
    r1.z = fmaxf(fmaf(v1.z, a0, q0), fmaf(v1.z, a1, q1));
    r1.w = fmaxf(fmaf(v1.w, a0, q0), fmaf(v1.w, a1, q1));
    r2.x = fmaxf(fmaf(v2.x, a0, q0), fmaf(v2.x, a1, q1));
    r2.y = fmaxf(fmaf(v2.y, a0, q0), fmaf(v2.y, a1, q1));
    r2.z = fmaxf(fmaf(v2.z, a0, q0), fmaf(v2.z, a1, q1));
    r2.w = fmaxf(fmaf(v2.w, a0, q0), fmaf(v2.w, a1, q1));
    r3.x = fmaxf(fmaf(v3.x, a0, q0), fmaf(v3.x, a1, q1));
    r3.y = fmaxf(fmaf(v3.y, a0, q0), fmaf(v3.y, a1, q1));
    r3.z = fmaxf(fmaf(v3.z, a0, q0), fmaf(v3.z, a1, q1));
    r3.w = fmaxf(fmaf(v3.w, a0, q0), fmaf(v3.w, a1, q1));

    // Evict-first streaming stores: keep x resident in L2, not out.
    __stcs(&o4[t],       r0);
    __stcs(&o4[t + 256], r1);
    __stcs(&o4[t + 512], r2);
    __stcs(&o4[t + 768], r3);
}

extern "C" void kernel_launch(void* const* d_in, const int* in_sizes, int n_in,
                              void* d_out, int out_size) {
    const float* x  = (const float*)d_in[0];
    const float* w1 = (const float*)d_in[1];
    const float* b1 = (const float*)d_in[2];
    const float* w2 = (const float*)d_in[3];
    const float* b2 = (const float*)d_in[4];
    float* out = (float*)d_out;

    pool_kernel<<<NPLANES, 256>>>(x);
    coef_kernel<<<BS, 256>>>(w1, b1, w2, b2);
    apply_kernel<<<NPLANES, 256>>>(x, out);
}